// round 17
// baseline (speedup 1.0000x reference)
#include <cuda_runtime.h>
#include <cuda_bf16.h>

typedef unsigned int u32;
typedef unsigned long long u64;

// Fixed problem shape
#define NMAX 100000
#define QMAX 256
#define RMAX 401

// Scratch (device globals — no allocation allowed)
__device__ float g_tableS[NMAX * 64];
__device__ float g_tableR[RMAX * 64];
__device__ float g_tableQ[QMAX * 64];
__device__ float g_tableQR[QMAX * RMAX * 64];
__device__ float g_agg[NMAX * 64];
__device__ int   g_flag;          // small-table completion counter (reset by final GEMM)

// ---- helpers ----
__device__ __forceinline__ u32 pack_bf2(float lo, float hi) {
    __nv_bfloat162 t = __floats2bfloat162_rn(lo, hi);
    return *(u32*)&t;
}
__device__ __forceinline__ void split_bf(float x, float& hi, float& lo) {
    __nv_bfloat16 h = __float2bfloat16_rn(x);
    hi = __bfloat162float(h);
    lo = x - hi;
}
__device__ __forceinline__ u32 prmt_hi16(u32 a, u32 b) {
    u32 d;
    asm("prmt.b32 %0, %1, %2, 0x7632;" : "=r"(d) : "r"(a), "r"(b));
    return d;
}
// truncation split of 2 floats -> bf16x2 hi-pack + lo-pack
__device__ __forceinline__ void split2(float x0, float x1, u32& hp, u32& lp) {
    u32 b0 = __float_as_uint(x0), b1 = __float_as_uint(x1);
    hp = prmt_hi16(b0, b1);
    float l0 = x0 - __uint_as_float(b0 & 0xFFFF0000u);
    float l1 = x1 - __uint_as_float(b1 & 0xFFFF0000u);
    lp = prmt_hi16(__float_as_uint(l0), __float_as_uint(l1));
}

// 32-byte evict_last load (sm_103a requires .v4.b64 width for this hint)
__device__ __forceinline__ void ldg_el32B(const float* p, float4& lo, float4& hi) {
    u64 a, b, c, d;
    asm("ld.global.nc.L2::evict_last.v4.b64 {%0,%1,%2,%3}, [%4];"
        : "=l"(a), "=l"(b), "=l"(c), "=l"(d) : "l"(p));
    lo.x = __uint_as_float((u32)a); lo.y = __uint_as_float((u32)(a >> 32));
    lo.z = __uint_as_float((u32)b); lo.w = __uint_as_float((u32)(b >> 32));
    hi.x = __uint_as_float((u32)c); hi.y = __uint_as_float((u32)(c >> 32));
    hi.z = __uint_as_float((u32)d); hi.w = __uint_as_float((u32)(d >> 32));
}
__device__ __forceinline__ int2 ldg_cs2(const int2* p) {
    int2 v;
    asm("ld.global.cs.v2.s32 {%0,%1}, [%2];" : "=r"(v.x), "=r"(v.y) : "l"(p));
    return v;
}
__device__ __forceinline__ void stg_cs(float* p, float v) {
    asm volatile("st.global.cs.f32 [%0], %1;" :: "l"(p), "f"(v) : "memory");
}

// mma.sync m16n8k16 bf16, fp32 accumulate
__device__ __forceinline__ void mma16816(float c[4], const u32 a[4], u32 b0, u32 b1) {
    asm volatile(
        "mma.sync.aligned.m16n8k16.row.col.f32.bf16.bf16.f32 "
        "{%0,%1,%2,%3}, {%4,%5,%6,%7}, {%8,%9}, {%0,%1,%2,%3};"
        : "+f"(c[0]), "+f"(c[1]), "+f"(c[2]), "+f"(c[3])
        : "r"(a[0]), "r"(a[1]), "r"(a[2]), "r"(a[3]), "r"(b0), "r"(b1));
}
__device__ __forceinline__ void ldmatrix_x4(u32 a[4], u32 addr) {
    asm volatile("ldmatrix.sync.aligned.m8n8.x4.shared.b16 {%0,%1,%2,%3}, [%4];"
                 : "=r"(a[0]), "=r"(a[1]), "=r"(a[2]), "=r"(a[3]) : "r"(addr));
}

// -----------------------------------------------------------------------------
// Persistent, double-buffered tensor-core 64x64 NT GEMM (bf16 hi/lo, 3 MMAs).
// Round-10 structure: v[8] batched staging, split accumulators.
// MODE 0: X from gmem; optional bias; optional zbuf zeroing (fused agg clear).
// MODE 1: X row p=(q,r) = q_emb[q]*rela[r]; epilogue adds tR[r]+tQ[q].
// -----------------------------------------------------------------------------
template<int MODE>
__device__ __forceinline__
void gemm_body(const float* __restrict__ X,
               const float* __restrict__ qe,
               const float* __restrict__ re,
               const float* __restrict__ W,
               const float* __restrict__ bias,
               const float* __restrict__ tR,
               const float* __restrict__ tQ,
               float* __restrict__ out, int M, int R,
               float4* __restrict__ zbuf, int tiles,
               int tile0, int stride)
{
    extern __shared__ unsigned char sX[];   // [2 bufs][hi 16KB | lo 16KB] = 64 KB
    const int tid  = threadIdx.x;
    const int lane = tid & 31;
    const int w    = tid >> 5;
    const int cg   = w & 3;
    const int rg   = w >> 2;

    // ---- W fragments (hi/lo) in registers: built once per CTA ----
    u32 Bhi[2][4][2], Blo[2][4][2];
    {
        const int n_base = cg * 16 + (lane >> 2);
        const int k_base = (lane & 3) * 2;
        #pragma unroll
        for (int nt = 0; nt < 2; nt++) {
            #pragma unroll
            for (int ks = 0; ks < 4; ks++) {
                const float* wr = &W[(n_base + nt * 8) * 64 + ks * 16 + k_base];
                float w0 = __ldg(wr),     w1 = __ldg(wr + 1);
                float w2 = __ldg(wr + 8), w3 = __ldg(wr + 9);
                float h0, l0, h1, l1, h2, l2, h3, l3;
                split_bf(w0, h0, l0); split_bf(w1, h1, l1);
                split_bf(w2, h2, l2); split_bf(w3, h3, l3);
                Bhi[nt][ks][0] = pack_bf2(h0, h1); Bhi[nt][ks][1] = pack_bf2(h2, h3);
                Blo[nt][ks][0] = pack_bf2(l0, l1); Blo[nt][ks][1] = pack_bf2(l2, l3);
            }
        }
    }

    const u32 sb = (u32)__cvta_generic_to_shared(sX);
    const int mi = lane >> 3, lr = lane & 7;
    const int row_off = (mi & 1) * 8 + lr;
    const int kb_off  = (mi >> 1) * 16;
    const int srow = tid >> 4, sc4 = tid & 15;

    // ---- staging helpers (batched loads for MLP) ----
    auto stage_load = [&](int tile, float4 v[8]) {
        const int p0 = tile * 128 + srow;
        int q = 0, r = 0;
        if (MODE == 1) { q = p0 / R; r = p0 - q * R; }
        #pragma unroll
        for (int j = 0; j < 8; j++) {
            int p = p0 + j * 16;
            float4 t = make_float4(0.f, 0.f, 0.f, 0.f);
            if (p < M) {
                if (MODE == 0) {
                    t = __ldg(&((const float4*)X)[(size_t)p * 16 + sc4]);
                    if (zbuf) zbuf[(size_t)p * 16 + sc4] = make_float4(0.f, 0.f, 0.f, 0.f);
                } else {
                    float4 a = __ldg(&((const float4*)qe)[q * 16 + sc4]);
                    float4 b = __ldg(&((const float4*)re)[r * 16 + sc4]);
                    t = make_float4(a.x * b.x, a.y * b.y, a.z * b.z, a.w * b.w);
                }
            }
            v[j] = t;
            if (MODE == 1) { r += 16; if (r >= R) { r -= R; q++; } }
        }
    };
    auto stage_store = [&](const float4 v[8], int buf) {
        unsigned char* base = sX + buf * 32768;
        #pragma unroll
        for (int j = 0; j < 8; j++) {
            int row = srow + j * 16;
            u32 off = (u32)(row * 128 + ((sc4 * 8) ^ ((row & 7) << 4)));
            u32 h0, l0, h1, l1;
            split2(v[j].x, v[j].y, h0, l0);
            split2(v[j].z, v[j].w, h1, l1);
            *(uint2*)(base + off)         = make_uint2(h0, h1);
            *(uint2*)(base + 16384 + off) = make_uint2(l0, l1);
        }
    };

    auto mma_epilogue = [&](int buf, int m0b) {
        const u32 hi_base = sb + buf * 32768;
        int q0 = 0, rr0 = 0, q1 = 0, rr1 = 0;
        if (MODE == 1) {
            int p0 = m0b + rg * 64 + (lane >> 2);
            q0 = p0 / R; rr0 = p0 - q0 * R;
            int p1 = p0 + 8;
            q1 = p1 / R; rr1 = p1 - q1 * R;
        }
        #pragma unroll
        for (int mt = 0; mt < 4; mt++) {
            const int mrow = rg * 64 + mt * 16;
            float accA[2][4] = {{0.f,0.f,0.f,0.f},{0.f,0.f,0.f,0.f}};
            float accB[2][4] = {{0.f,0.f,0.f,0.f},{0.f,0.f,0.f,0.f}};
            #pragma unroll
            for (int ks = 0; ks < 4; ks++) {
                const int row = mrow + row_off;
                const u32 byte = (u32)(row * 128 + ((ks * 32 + kb_off) ^ ((row & 7) << 4)));
                u32 Ahi[4], Alo[4];
                ldmatrix_x4(Ahi, hi_base + byte);
                ldmatrix_x4(Alo, hi_base + 16384 + byte);
                #pragma unroll
                for (int nt = 0; nt < 2; nt++) {
                    mma16816(accA[nt], Ahi, Bhi[nt][ks][0], Bhi[nt][ks][1]);
                    mma16816(accB[nt], Ahi, Blo[nt][ks][0], Blo[nt][ks][1]);
                    mma16816(accB[nt], Alo, Bhi[nt][ks][0], Bhi[nt][ks][1]);
                }
            }
            const int r0 = m0b + mrow + (lane >> 2);
            const int r1 = r0 + 8;
            #pragma unroll
            for (int nt = 0; nt < 2; nt++) {
                const int col = cg * 16 + nt * 8 + (lane & 3) * 2;
                float2 e0 = make_float2(accA[nt][0] + accB[nt][0], accA[nt][1] + accB[nt][1]);
                float2 e1 = make_float2(accA[nt][2] + accB[nt][2], accA[nt][3] + accB[nt][3]);
                if (MODE == 0) {
                    if (bias) {
                        float2 bv = *(const float2*)&bias[col];
                        e0.x += bv.x; e0.y += bv.y; e1.x += bv.x; e1.y += bv.y;
                    }
                } else {
                    if (r0 < M) {
                        float2 t1 = __ldg((const float2*)&tR[rr0 * 64 + col]);
                        float2 t2 = __ldg((const float2*)&tQ[q0 * 64 + col]);
                        e0.x += t1.x + t2.x; e0.y += t1.y + t2.y;
                    }
                    if (r1 < M) {
                        float2 t1 = __ldg((const float2*)&tR[rr1 * 64 + col]);
                        float2 t2 = __ldg((const float2*)&tQ[q1 * 64 + col]);
                        e1.x += t1.x + t2.x; e1.y += t1.y + t2.y;
                    }
                }
                if (r0 < M) *(float2*)&out[(size_t)r0 * 64 + col] = e0;
                if (r1 < M) *(float2*)&out[(size_t)r1 * 64 + col] = e1;
            }
            if (MODE == 1) {
                rr0 += 16; if (rr0 >= R) { rr0 -= R; q0++; }
                rr1 += 16; if (rr1 >= R) { rr1 -= R; q1++; }
            }
        }
    };

    // ---- persistent pipelined loop ----
    int tile = tile0;
    if (tile < tiles) {
        float4 v[8];
        stage_load(tile, v);
        stage_store(v, 0);
    }
    __syncthreads();
    int cur = 0;
    while (tile < tiles) {
        const int nxt = tile + stride;
        const bool have = (nxt < tiles);
        float4 v[8];
        if (have) stage_load(nxt, v);
        mma_epilogue(cur, tile * 128);
        if (have) stage_store(v, cur ^ 1);
        __syncthreads();
        cur ^= 1;
        tile = nxt;
    }
}

// ---- global wrappers ----
// Final projection; also resets g_flag for the next replay (stream-ordered
// after the mid kernel's handshake, before the next call's launch).
__global__ __launch_bounds__(256, 2)
void gemm_tc0(const float* __restrict__ X, const float* __restrict__ W,
              const float* __restrict__ bias, float* __restrict__ out,
              int M, float4* __restrict__ zbuf, int tiles, int reset_flag)
{
    if (reset_flag && blockIdx.x == 0 && threadIdx.x == 0) g_flag = 0;
    gemm_body<0>(X, nullptr, nullptr, W, bias, nullptr, nullptr,
                 out, M, 1, zbuf, tiles, blockIdx.x, gridDim.x);
}

// Merged mid launch — three CTA groups:
//   [0, nSmall):           small table GEMMs (tR, tQ); release g_flag on finish
//   [nSmall, nSmall+gA):   tS GEMM (MODE 0, also zeroes agg)
//   [nSmall+gA, grid):     tQR GEMM (MODE 1); acquires g_flag before running
__global__ __launch_bounds__(256, 2)
void gemm_mid_tri(const float* __restrict__ rela_in, const float* __restrict__ Wr_W,
                  float* __restrict__ tR, int Rrows, int tilesR,
                  const float* __restrict__ qe_in, const float* __restrict__ Wq_W,
                  float* __restrict__ tQ, int Qrows, int tilesQ,
                  const float* __restrict__ hidden, const float* __restrict__ Ws_W,
                  const float* __restrict__ Ws_b, float* __restrict__ tS,
                  int N, float4* __restrict__ zbuf, int tilesA, int gridA,
                  const float* __restrict__ qe, const float* __restrict__ re,
                  const float* __restrict__ Wqr, float* __restrict__ tQR,
                  int MQR, int R, int tilesB)
{
    const int nSmall = tilesR + tilesQ;
    const int bid = blockIdx.x;

    if (bid < nSmall) {
        if (bid < tilesR)
            gemm_body<0>(rela_in, nullptr, nullptr, Wr_W, nullptr, nullptr, nullptr,
                         tR, Rrows, 1, nullptr, tilesR, bid, 1 << 20);
        else
            gemm_body<0>(qe_in, nullptr, nullptr, Wq_W, nullptr, nullptr, nullptr,
                         tQ, Qrows, 1, nullptr, tilesQ, bid - tilesR, 1 << 20);
        __threadfence();            // release: table writes visible before count
        __syncthreads();
        if (threadIdx.x == 0) atomicAdd(&g_flag, 1);
    } else if (bid < nSmall + gridA) {
        gemm_body<0>(hidden, nullptr, nullptr, Ws_W, Ws_b, nullptr, nullptr,
                     tS, N, 1, zbuf, tilesA, bid - nSmall, gridA);
    } else {
        // acquire: wait for all small-table CTAs before reading tR/tQ
        if (threadIdx.x == 0) {
            while (atomicAdd(&g_flag, 0) < nSmall) __nanosleep(200);
        }
        __syncthreads();
        __threadfence();
        gemm_body<1>(nullptr, qe, re, Wqr, nullptr, tR, tQ,
                     tQR, MQR, R, nullptr, tilesB,
                     bid - nSmall - gridA, gridDim.x - nSmall - gridA);
    }
}

// -----------------------------------------------------------------------------
// Edge kernel: 8 lanes (quarter-warp) per edge, 8 floats (32 B) per lane.
// Table gathers (tS, tQR) use 32-byte evict_last loads to keep the reused
// tables resident in L2 against the streaming edge/alpha/agg traffic.
// -----------------------------------------------------------------------------
__global__ __launch_bounds__(256)
void edge_kernel(const int* __restrict__ edges,
                 const float* __restrict__ hidden,
                 const float* __restrict__ rela,
                 const float* __restrict__ wa_W,
                 const float* __restrict__ wa_b,
                 const float* __restrict__ tS,
                 const float* __restrict__ tQR,
                 float* __restrict__ agg,
                 float* __restrict__ alpha_out,
                 int E, int R)
{
    const int t = blockIdx.x * 256 + threadIdx.x;
    const int e = t >> 3;
    if (e >= E) return;
    const int sl = t & 7;            // lane within 8-lane group
    const int c0 = sl * 8;           // first float of this lane's 32B chunk

    // edges row = [q,h,r,t,s,o]: three aligned int2 streaming loads
    const int2* e2 = (const int2*)(edges + (size_t)e * 6);
    const int2 i0 = ldg_cs2(e2 + 0);   // (q, h)
    const int2 i1 = ldg_cs2(e2 + 1);   // (r, t)
    const int2 i2 = ldg_cs2(e2 + 2);   // (s, o)
    const int q = i0.x, r = i1.x, s = i2.x, o = i2.y;

    float4 g0, g1, p0, p1;
    ldg_el32B(tS  + (size_t)s * 64 + c0, g0, g1);
    ldg_el32B(tQR + ((size_t)q * R + r) * 64 + c0, p0, p1);
    float4 hs0 = __ldg((const float4*)(hidden + (size_t)s * 64 + c0));
    float4 hs1 = __ldg((const float4*)(hidden + (size_t)s * 64 + c0) + 1);
    float4 hr0 = __ldg((const float4*)(rela + (size_t)r * 64 + c0));
    float4 hr1 = __ldg((const float4*)(rela + (size_t)r * 64 + c0) + 1);
    float4 wa0 = __ldg((const float4*)(wa_W + c0));
    float4 wa1 = __ldg((const float4*)(wa_W + c0) + 1);

    float part =
        fmaf(fmaxf(g0.x + p0.x, 0.f), wa0.x,
        fmaf(fmaxf(g0.y + p0.y, 0.f), wa0.y,
        fmaf(fmaxf(g0.z + p0.z, 0.f), wa0.z,
        fmaf(fmaxf(g0.w + p0.w, 0.f), wa0.w,
        fmaf(fmaxf(g1.x + p1.x, 0.f), wa1.x,
        fmaf(fmaxf(g1.y + p1.y, 0.f), wa1.y,
        fmaf(fmaxf(g1.z + p1.z, 0.f), wa1.z,
             fmaxf(g1.w + p1.w, 0.f) * wa1.w)))))));

    #pragma unroll
    for (int off = 4; off; off >>= 1)
        part += __shfl_xor_sync(0xffffffffu, part, off);

    const float alpha = 1.0f / (1.0f + __expf(-(part + __ldg(wa_b))));
    if (sl == 0) stg_cs(&alpha_out[e], alpha);

    float4 m0 = make_float4(alpha * hs0.x * hr0.x, alpha * hs0.y * hr0.y,
                            alpha * hs0.z * hr0.z, alpha * hs0.w * hr0.w);
    float4 m1 = make_float4(alpha * hs1.x * hr1.x, alpha * hs1.y * hr1.y,
                            alpha * hs1.z * hr1.z, alpha * hs1.w * hr1.w);

    float* dst = &agg[(size_t)o * 64 + c0];
    asm volatile("red.global.add.v4.f32 [%0], {%1, %2, %3, %4};"
                 :: "l"(dst), "f"(m0.x), "f"(m0.y), "f"(m0.z), "f"(m0.w) : "memory");
    asm volatile("red.global.add.v4.f32 [%0], {%1, %2, %3, %4};"
                 :: "l"(dst + 4), "f"(m1.x), "f"(m1.y), "f"(m1.z), "f"(m1.w) : "memory");
}

// -----------------------------------------------------------------------------
extern "C" void kernel_launch(void* const* d_in, const int* in_sizes, int n_in,
                              void* d_out, int out_size)
{
    const float* q_emb  = (const float*)d_in[1];
    const float* rela   = (const float*)d_in[2];
    const float* hidden = (const float*)d_in[3];
    const int*   edges  = (const int*)d_in[4];
    const float* Ws_W   = (const float*)d_in[6];
    const float* Ws_b   = (const float*)d_in[7];
    const float* Wr_W   = (const float*)d_in[8];
    const float* Wq_W   = (const float*)d_in[9];
    const float* Wqr_W  = (const float*)d_in[10];
    const float* wa_W   = (const float*)d_in[11];
    const float* wa_b   = (const float*)d_in[12];
    const float* Wh_W   = (const float*)d_in[13];

    const int Q = in_sizes[0];
    const int R = in_sizes[2] / 64;
    const int N = in_sizes[3] / 64;
    const int E = in_sizes[4] / 6;

    float* out = (float*)d_out;
    float* alpha_out = out + (size_t)N * 64;

    float *tS, *tR, *tQ, *tQR, *agg;
    cudaGetSymbolAddress((void**)&tS,  g_tableS);
    cudaGetSymbolAddress((void**)&tR,  g_tableR);
    cudaGetSymbolAddress((void**)&tQ,  g_tableQ);
    cudaGetSymbolAddress((void**)&tQR, g_tableQR);
    cudaGetSymbolAddress((void**)&agg, g_agg);

    const int SMEM = 65536;   // 2 x (hi 16KB + lo 16KB)
    cudaFuncSetAttribute(gemm_tc0, cudaFuncAttributeMaxDynamicSharedMemorySize, SMEM);
    cudaFuncSetAttribute(gemm_mid_tri, cudaFuncAttributeMaxDynamicSharedMemorySize, SMEM);

    auto tiles_of = [](int M) { return (M + 127) / 128; };
    auto grid_of  = [&](int M) { int t = tiles_of(M); return t < 296 ? t : 296; };

    // Mid phase: ONE launch — small tables + tS (also zeroes agg) + tQR,
    // with in-kernel release/acquire between small tables and tQR.
    const int tilesR = tiles_of(R), tilesQ = tiles_of(Q);
    const int nSmall = tilesR + tilesQ;           // 6
    const int gridA = 200, gridB = 238;           // tS : tQR CTA split
    gemm_mid_tri<<<nSmall + gridA + gridB, 256, SMEM>>>(
        rela, Wr_W, tR, R, tilesR,
        q_emb, Wq_W, tQ, Q, tilesQ,
        hidden, Ws_W, Ws_b, tS, N, (float4*)agg, tiles_of(N), gridA,
        q_emb, rela, Wqr_W, tQR, Q * R, R, tiles_of(Q * R));

    // Per-edge gather/gate/scatter (8 lanes per edge, evict_last table gathers)
    edge_kernel<<<(E * 8 + 255) / 256, 256>>>(edges, hidden, rela, wa_W, wa_b,
                                              tS, tQR, agg, alpha_out, E, R);

    // Final projection: hidden_new = agg @ Wh^T (also resets g_flag)
    gemm_tc0<<<grid_of(N), 256, SMEM>>>(agg, Wh_W, nullptr, out, N,
                                        nullptr, tiles_of(N), 1);
}